// round 3
// baseline (speedup 1.0000x reference)
#include <cuda_runtime.h>

#define NN 50000
#define NE 800000
#define NTOT (NE + NN)
#define NF 128
#define NH 256
#define NC 40
#define KHOPS 10

// ---------------- device scratch (static, no runtime alloc) ----------------
__device__ int   g_mode;           // 1 = edge_index is int64, 0 = int32
__device__ int   g_esrc[NE];
__device__ int   g_edst[NE];
__device__ int   g_cnt[NN];
__device__ int   g_ptr[NN + 1];
__device__ int   g_bsums[64];
__device__ float g_dinv[NN];
__device__ int   g_src[NTOT];
__device__ __align__(16) float g_w[NTOT];
__device__ __align__(16) float g_h0[NN * NF];
__device__ __align__(16) float g_h1[NN * NF];
__device__ __align__(16) float g_hidden[NN * NF];
__device__ __align__(16) float g_z1[(size_t)NN * NH];

// ---------------- edge dtype detection + conversion ----------------
__global__ void k_detect(const void* __restrict__ ei) {
    if (threadIdx.x == 0 && blockIdx.x == 0) {
        const long long* p = (const long long*)ei;
        int ok = 1;
        for (int i = 0; i < 256; i++) {
            long long v = p[i];
            if (v < 0 || v >= NN) { ok = 0; break; }
        }
        g_mode = ok;
    }
}

__global__ void k_convert(const void* __restrict__ ei) {
    int i = blockIdx.x * blockDim.x + threadIdx.x;
    if (i >= NE) return;
    if (g_mode) {
        const long long* p = (const long long*)ei;
        g_esrc[i] = (int)p[i];
        g_edst[i] = (int)p[NE + i];
    } else {
        const int* p = (const int*)ei;
        g_esrc[i] = p[i];
        g_edst[i] = p[NE + i];
    }
}

// ---------------- degree / CSR build ----------------
__global__ void k_initcnt() {
    int i = blockIdx.x * blockDim.x + threadIdx.x;
    if (i < NN) g_cnt[i] = 1;  // self loop
}

__global__ void k_count() {
    int i = blockIdx.x * blockDim.x + threadIdx.x;
    if (i < NE) {
        unsigned c = (unsigned)g_edst[i];
        if (c < NN) atomicAdd(&g_cnt[c], 1);
    }
}

__global__ void k_dinv() {
    int i = blockIdx.x * blockDim.x + threadIdx.x;
    if (i < NN) g_dinv[i] = rsqrtf((float)g_cnt[i]);
}

__global__ void k_scan1() {
    __shared__ int sh[2][1024];
    int tid = threadIdx.x;
    int i = blockIdx.x * 1024 + tid;
    int v = (i < NN) ? g_cnt[i] : 0;
    int buf = 0;
    sh[0][tid] = v;
    __syncthreads();
#pragma unroll
    for (int off = 1; off < 1024; off <<= 1) {
        sh[buf ^ 1][tid] = sh[buf][tid] + ((tid >= off) ? sh[buf][tid - off] : 0);
        buf ^= 1;
        __syncthreads();
    }
    if (i < NN) g_ptr[i] = sh[buf][tid] - v;  // block-local exclusive
    if (tid == 1023) g_bsums[blockIdx.x] = sh[buf][1023];
}

__global__ void k_scan2(int nb) {
    if (threadIdx.x == 0 && blockIdx.x == 0) {
        int run = 0;
        for (int b = 0; b < nb; b++) { int t = g_bsums[b]; g_bsums[b] = run; run += t; }
        g_ptr[NN] = run;
    }
}

__global__ void k_scan3() {
    int i = blockIdx.x * 1024 + threadIdx.x;
    if (i < NN) g_ptr[i] += g_bsums[blockIdx.x];
}

__global__ void k_zerocnt() {
    int i = blockIdx.x * blockDim.x + threadIdx.x;
    if (i < NN) g_cnt[i] = 0;
}

__global__ void k_fill() {
    int i = blockIdx.x * blockDim.x + threadIdx.x;
    if (i < NE) {
        unsigned r = (unsigned)g_esrc[i];
        unsigned c = (unsigned)g_edst[i];
        if (r < NN && c < NN) {
            int pos = g_ptr[c] + atomicAdd(&g_cnt[c], 1);
            g_src[pos] = (int)r;
            g_w[pos] = g_dinv[r] * g_dinv[c];
        }
    } else if (i < NTOT) {
        int n = i - NE;
        int pos = g_ptr[n] + atomicAdd(&g_cnt[n], 1);
        g_src[pos] = n;
        float d = g_dinv[n];
        g_w[pos] = d * d;
    }
}

// ---------------- init h0 = x, hidden = temp[0]*x ----------------
__global__ void k_init_h(const float* __restrict__ x, const float* __restrict__ temp) {
    int i = blockIdx.x * blockDim.x + threadIdx.x;  // float4 index
    if (i < NN * NF / 4) {
        float t0 = temp[0];
        float4 v = ((const float4*)x)[i];
        ((float4*)g_h0)[i] = v;
        float4 hv = make_float4(t0 * v.x, t0 * v.y, t0 * v.z, t0 * v.w);
        ((float4*)g_hidden)[i] = hv;
    }
}

// ---------------- one propagation hop: warp per node ----------------
__global__ void k_prop(const float* __restrict__ temp, int k) {
    const float* __restrict__ hin = (k & 1) ? g_h1 : g_h0;
    float* __restrict__ hout      = (k & 1) ? g_h0 : g_h1;
    int node = blockIdx.x * 8 + (threadIdx.x >> 5);
    if (node >= NN) return;
    int lane = threadIdx.x & 31;
    int beg = __ldg(&g_ptr[node]), end = __ldg(&g_ptr[node + 1]);
    float tk = __ldg(&temp[k + 1]);

    float4 acc = make_float4(0.f, 0.f, 0.f, 0.f);
    int e = beg;
    for (; e + 3 < end; e += 4) {
        int s0 = __ldg(&g_src[e]),     s1 = __ldg(&g_src[e + 1]);
        int s2 = __ldg(&g_src[e + 2]), s3 = __ldg(&g_src[e + 3]);
        float w0 = __ldg(&g_w[e]),     w1 = __ldg(&g_w[e + 1]);
        float w2 = __ldg(&g_w[e + 2]), w3 = __ldg(&g_w[e + 3]);
        float4 v0 = ((const float4*)(hin + (size_t)s0 * NF))[lane];
        float4 v1 = ((const float4*)(hin + (size_t)s1 * NF))[lane];
        float4 v2 = ((const float4*)(hin + (size_t)s2 * NF))[lane];
        float4 v3 = ((const float4*)(hin + (size_t)s3 * NF))[lane];
        acc.x += w0 * v0.x + w1 * v1.x + w2 * v2.x + w3 * v3.x;
        acc.y += w0 * v0.y + w1 * v1.y + w2 * v2.y + w3 * v3.y;
        acc.z += w0 * v0.z + w1 * v1.z + w2 * v2.z + w3 * v3.z;
        acc.w += w0 * v0.w + w1 * v1.w + w2 * v2.w + w3 * v3.w;
    }
    for (; e < end; e++) {
        int s = __ldg(&g_src[e]);
        float w = __ldg(&g_w[e]);
        float4 v = ((const float4*)(hin + (size_t)s * NF))[lane];
        acc.x += w * v.x; acc.y += w * v.y; acc.z += w * v.z; acc.w += w * v.w;
    }
    size_t o = (size_t)node * (NF / 4) + lane;
    ((float4*)hout)[o] = acc;
    float4 hv = ((float4*)g_hidden)[o];
    hv.x += tk * acc.x; hv.y += tk * acc.y; hv.z += tk * acc.z; hv.w += tk * acc.w;
    ((float4*)g_hidden)[o] = hv;
}

// ---------------- MLP layer 1: z1 = relu(hidden @ W1 + b1) ----------------
__global__ void k_mlp1(const float* __restrict__ B, const float* __restrict__ bias) {
    __shared__ float As[64][33];
    __shared__ float Bs[32][64];
    const float* __restrict__ A = g_hidden;
    float* __restrict__ C = g_z1;

    int tid = threadIdx.x;
    int brow = blockIdx.x * 64;
    int bcol = blockIdx.y * 64;
    int tr = (tid / 16) * 4;
    int tc = (tid % 16) * 4;

    float acc[4][4];
#pragma unroll
    for (int i = 0; i < 4; i++)
#pragma unroll
        for (int j = 0; j < 4; j++) acc[i][j] = 0.f;

    for (int k0 = 0; k0 < NF; k0 += 32) {
#pragma unroll
        for (int t = 0; t < 2; t++) {
            int i = tid + t * 256;
            int r = i / 8, c = (i % 8) * 4;
            float4 v;
            if (brow + r < NN)
                v = *(const float4*)&A[(size_t)(brow + r) * NF + k0 + c];
            else
                v = make_float4(0.f, 0.f, 0.f, 0.f);
            As[r][c] = v.x; As[r][c + 1] = v.y; As[r][c + 2] = v.z; As[r][c + 3] = v.w;
        }
#pragma unroll
        for (int t = 0; t < 2; t++) {
            int i = tid + t * 256;
            int r = i / 16, c = (i % 16) * 4;
            float4 v = *(const float4*)&B[(size_t)(k0 + r) * NH + bcol + c];
            *(float4*)&Bs[r][c] = v;
        }
        __syncthreads();
#pragma unroll
        for (int kk = 0; kk < 32; kk++) {
            float a[4];
#pragma unroll
            for (int i = 0; i < 4; i++) a[i] = As[tr + i][kk];
            float4 b = *(const float4*)&Bs[kk][tc];
#pragma unroll
            for (int i = 0; i < 4; i++) {
                acc[i][0] += a[i] * b.x;
                acc[i][1] += a[i] * b.y;
                acc[i][2] += a[i] * b.z;
                acc[i][3] += a[i] * b.w;
            }
        }
        __syncthreads();
    }

    float4 bb = *(const float4*)&bias[bcol + tc];
#pragma unroll
    for (int i = 0; i < 4; i++) {
        int r = brow + tr + i;
        if (r < NN) {
            float4 v;
            v.x = fmaxf(acc[i][0] + bb.x, 0.f);
            v.y = fmaxf(acc[i][1] + bb.y, 0.f);
            v.z = fmaxf(acc[i][2] + bb.z, 0.f);
            v.w = fmaxf(acc[i][3] + bb.w, 0.f);
            *(float4*)&C[(size_t)r * NH + bcol + tc] = v;
        }
    }
}

// ---------------- MLP layer 2 + log_softmax: thread per node ----------------
__global__ void k_mlp2(const float* __restrict__ W2, const float* __restrict__ b2,
                       float* __restrict__ out) {
    __shared__ float Ws[NH * NC];
    __shared__ float bs[NC];
    for (int i = threadIdx.x; i < NH * NC; i += blockDim.x) Ws[i] = W2[i];
    if (threadIdx.x < NC) bs[threadIdx.x] = b2[threadIdx.x];
    __syncthreads();

    int node = blockIdx.x * blockDim.x + threadIdx.x;
    if (node >= NN) return;

    float acc[NC];
#pragma unroll
    for (int j = 0; j < NC; j++) acc[j] = bs[j];

    const float4* z4 = (const float4*)(g_z1 + (size_t)node * NH);
    for (int kk = 0; kk < NH / 4; kk++) {
        float4 z = z4[kk];
        int base = (kk * 4) * NC;
#pragma unroll
        for (int j = 0; j < NC; j++) {
            acc[j] += z.x * Ws[base + j] + z.y * Ws[base + NC + j]
                    + z.z * Ws[base + 2 * NC + j] + z.w * Ws[base + 3 * NC + j];
        }
    }

    float m = -1e30f;
#pragma unroll
    for (int j = 0; j < NC; j++) m = fmaxf(m, acc[j]);
    float s = 0.f;
#pragma unroll
    for (int j = 0; j < NC; j++) s += expf(acc[j] - m);
    float ls = logf(s);
    float* o = out + (size_t)node * NC;
#pragma unroll
    for (int j = 0; j < NC; j++) o[j] = acc[j] - m - ls;
}

// ---------------- launch ----------------
extern "C" void kernel_launch(void* const* d_in, const int* in_sizes, int n_in,
                              void* d_out, int out_size) {
    const float* x    = (const float*)d_in[0];
    const void*  ei   = d_in[1];
    const float* temp = (const float*)d_in[2];
    const float* W1   = (const float*)d_in[3];
    const float* b1   = (const float*)d_in[4];
    const float* W2   = (const float*)d_in[5];
    const float* b2   = (const float*)d_in[6];
    float*       out  = (float*)d_out;

    const int TB = 256;
    const int NB_SCAN = (NN + 1023) / 1024;  // 49

    k_detect<<<1, 32>>>(ei);
    k_convert<<<(NE + TB - 1) / TB, TB>>>(ei);

    k_initcnt<<<(NN + TB - 1) / TB, TB>>>();
    k_count<<<(NE + TB - 1) / TB, TB>>>();
    k_dinv<<<(NN + TB - 1) / TB, TB>>>();
    k_scan1<<<NB_SCAN, 1024>>>();
    k_scan2<<<1, 32>>>(NB_SCAN);
    k_scan3<<<NB_SCAN, 1024>>>();
    k_zerocnt<<<(NN + TB - 1) / TB, TB>>>();
    k_fill<<<(NTOT + TB - 1) / TB, TB>>>();

    k_init_h<<<(NN * NF / 4 + TB - 1) / TB, TB>>>(x, temp);

    for (int k = 0; k < KHOPS; k++) {
        k_prop<<<(NN + 7) / 8, 256>>>(temp, k);
    }

    dim3 g1((NN + 63) / 64, NH / 64);
    k_mlp1<<<g1, 256>>>(W1, b1);

    k_mlp2<<<(NN + 127) / 128, 128>>>(W2, b2, out);
}

// round 4
// speedup vs baseline: 1.2284x; 1.2284x over previous
#include <cuda_runtime.h>
#include <cuda_fp16.h>

#define NN 50000
#define NE 800000
#define NTOT (NE + NN)
#define NF 128
#define NH 256
#define NC 40
#define KHOPS 10

// ---------------- device scratch (static, no runtime alloc) ----------------
__device__ int   g_mode;           // 1 = edge_index is int64, 0 = int32
__device__ int   g_esrc[NE];
__device__ int   g_edst[NE];
__device__ int   g_cnt[NN];
__device__ int   g_ptr[NN + 1];
__device__ int   g_bsums[64];
__device__ float g_dinv[NN];
__device__ int   g_src[NTOT];
__device__ __align__(16) float  g_w[NTOT];
__device__ __align__(16) __half g_h0[NN * NF];
__device__ __align__(16) __half g_h1[NN * NF];
__device__ __align__(16) float  g_hidden[NN * NF];
__device__ __align__(16) float  g_z1[(size_t)NN * NH];

// ---------------- edge dtype detection (parallel, no serial chain) --------
__global__ void k_detect(const void* __restrict__ ei) {
    const long long* p = (const long long*)ei;
    int t = threadIdx.x;
    int bad = 0;
#pragma unroll
    for (int i = 0; i < 8; i++) {
        long long v = p[t + i * 32];
        if (v < 0 || v >= NN) bad = 1;
    }
    unsigned m = __ballot_sync(0xFFFFFFFFu, bad);
    if (t == 0) g_mode = (m == 0) ? 1 : 0;
}

// ---------------- convert edges + count degrees (fused) ----------------
__global__ void k_initcnt() {
    int i = blockIdx.x * blockDim.x + threadIdx.x;
    if (i < NN) g_cnt[i] = 1;  // self loop
}

__global__ void k_convert(const void* __restrict__ ei) {
    int i = blockIdx.x * blockDim.x + threadIdx.x;
    if (i >= NE) return;
    int s, d;
    if (g_mode) {
        const long long* p = (const long long*)ei;
        s = (int)p[i];
        d = (int)p[NE + i];
    } else {
        const int* p = (const int*)ei;
        s = p[i];
        d = p[NE + i];
    }
    g_esrc[i] = s;
    g_edst[i] = d;
    if ((unsigned)d < NN) atomicAdd(&g_cnt[d], 1);
}

__global__ void k_dinv() {
    int i = blockIdx.x * blockDim.x + threadIdx.x;
    if (i < NN) g_dinv[i] = rsqrtf((float)g_cnt[i]);
}

__global__ void k_scan1() {
    __shared__ int sh[2][1024];
    int tid = threadIdx.x;
    int i = blockIdx.x * 1024 + tid;
    int v = (i < NN) ? g_cnt[i] : 0;
    int buf = 0;
    sh[0][tid] = v;
    __syncthreads();
#pragma unroll
    for (int off = 1; off < 1024; off <<= 1) {
        sh[buf ^ 1][tid] = sh[buf][tid] + ((tid >= off) ? sh[buf][tid - off] : 0);
        buf ^= 1;
        __syncthreads();
    }
    if (i < NN) g_ptr[i] = sh[buf][tid] - v;  // block-local exclusive
    if (tid == 1023) g_bsums[blockIdx.x] = sh[buf][1023];
}

__global__ void k_scan2(int nb) {  // 64 threads, shfl scan
    __shared__ int sh[2];
    int t = threadIdx.x;
    int lane = t & 31, w = t >> 5;
    int v = (t < nb) ? g_bsums[t] : 0;
    int x = v;
#pragma unroll
    for (int off = 1; off < 32; off <<= 1) {
        int y = __shfl_up_sync(0xFFFFFFFFu, x, off);
        if (lane >= off) x += y;
    }
    if (lane == 31) sh[w] = x;
    __syncthreads();
    if (w == 1) x += sh[0];
    if (t < nb) g_bsums[t] = x - v;  // exclusive
    if (t == nb - 1) g_ptr[NN] = x;
}

__global__ void k_scan3() {
    int i = blockIdx.x * 1024 + threadIdx.x;
    if (i < NN) g_ptr[i] += g_bsums[blockIdx.x];
}

__global__ void k_zerocnt() {
    int i = blockIdx.x * blockDim.x + threadIdx.x;
    if (i < NN) g_cnt[i] = 0;
}

__global__ void k_fill() {
    int i = blockIdx.x * blockDim.x + threadIdx.x;
    if (i < NE) {
        unsigned r = (unsigned)g_esrc[i];
        unsigned c = (unsigned)g_edst[i];
        if (r < NN && c < NN) {
            int pos = g_ptr[c] + atomicAdd(&g_cnt[c], 1);
            g_src[pos] = (int)r;
            g_w[pos] = g_dinv[r] * g_dinv[c];
        }
    } else if (i < NTOT) {
        int n = i - NE;
        int pos = g_ptr[n] + atomicAdd(&g_cnt[n], 1);
        g_src[pos] = n;
        float d = g_dinv[n];
        g_w[pos] = d * d;
    }
}

// ---------------- init h0 = fp16(x), hidden = temp[0]*x ----------------
__global__ void k_init_h(const float* __restrict__ x, const float* __restrict__ temp) {
    int i = blockIdx.x * blockDim.x + threadIdx.x;  // float4 index
    if (i < NN * NF / 4) {
        float t0 = temp[0];
        float4 v = ((const float4*)x)[i];
        __half2 p0 = __floats2half2_rn(v.x, v.y);
        __half2 p1 = __floats2half2_rn(v.z, v.w);
        float2 st;
        *(__half2*)&st.x = p0;
        *(__half2*)&st.y = p1;
        ((float2*)g_h0)[i] = st;
        float4 hv = make_float4(t0 * v.x, t0 * v.y, t0 * v.z, t0 * v.w);
        ((float4*)g_hidden)[i] = hv;
    }
}

// ---------------- one propagation hop: warp per node, fp16 rows -----------
__global__ void k_prop(const float* __restrict__ temp, int k) {
    const __half* __restrict__ hin = (k & 1) ? g_h1 : g_h0;
    __half* __restrict__ hout      = (k & 1) ? g_h0 : g_h1;
    int node = blockIdx.x * 8 + (threadIdx.x >> 5);
    if (node >= NN) return;
    int lane = threadIdx.x & 31;
    int beg = __ldg(&g_ptr[node]), end = __ldg(&g_ptr[node + 1]);
    float tk = __ldg(&temp[k + 1]);

    // lane owns features [lane*4, lane*4+4): 8 bytes fp16 per row
    float a0 = 0.f, a1 = 0.f, a2 = 0.f, a3 = 0.f;
    int e = beg;
    for (; e + 3 < end; e += 4) {
        int s0 = __ldg(&g_src[e]),     s1 = __ldg(&g_src[e + 1]);
        int s2 = __ldg(&g_src[e + 2]), s3 = __ldg(&g_src[e + 3]);
        float w0 = __ldg(&g_w[e]),     w1 = __ldg(&g_w[e + 1]);
        float w2 = __ldg(&g_w[e + 2]), w3 = __ldg(&g_w[e + 3]);
        float2 r0 = __ldg(&((const float2*)(hin + (size_t)s0 * NF))[lane]);
        float2 r1 = __ldg(&((const float2*)(hin + (size_t)s1 * NF))[lane]);
        float2 r2 = __ldg(&((const float2*)(hin + (size_t)s2 * NF))[lane]);
        float2 r3 = __ldg(&((const float2*)(hin + (size_t)s3 * NF))[lane]);
        {
            float2 fa = __half22float2(*(__half2*)&r0.x);
            float2 fb = __half22float2(*(__half2*)&r0.y);
            a0 += w0 * fa.x; a1 += w0 * fa.y; a2 += w0 * fb.x; a3 += w0 * fb.y;
        }
        {
            float2 fa = __half22float2(*(__half2*)&r1.x);
            float2 fb = __half22float2(*(__half2*)&r1.y);
            a0 += w1 * fa.x; a1 += w1 * fa.y; a2 += w1 * fb.x; a3 += w1 * fb.y;
        }
        {
            float2 fa = __half22float2(*(__half2*)&r2.x);
            float2 fb = __half22float2(*(__half2*)&r2.y);
            a0 += w2 * fa.x; a1 += w2 * fa.y; a2 += w2 * fb.x; a3 += w2 * fb.y;
        }
        {
            float2 fa = __half22float2(*(__half2*)&r3.x);
            float2 fb = __half22float2(*(__half2*)&r3.y);
            a0 += w3 * fa.x; a1 += w3 * fa.y; a2 += w3 * fb.x; a3 += w3 * fb.y;
        }
    }
    for (; e < end; e++) {
        int s = __ldg(&g_src[e]);
        float w = __ldg(&g_w[e]);
        float2 r = __ldg(&((const float2*)(hin + (size_t)s * NF))[lane]);
        float2 fa = __half22float2(*(__half2*)&r.x);
        float2 fb = __half22float2(*(__half2*)&r.y);
        a0 += w * fa.x; a1 += w * fa.y; a2 += w * fb.x; a3 += w * fb.y;
    }

    // store h_{k+1} as fp16
    {
        __half2 p0 = __floats2half2_rn(a0, a1);
        __half2 p1 = __floats2half2_rn(a2, a3);
        float2 st;
        *(__half2*)&st.x = p0;
        *(__half2*)&st.y = p1;
        ((float2*)(hout + (size_t)node * NF))[lane] = st;
    }
    // hidden += temp[k+1] * h_{k+1}  (fp32, from fp32 accumulators)
    {
        float4* hid = (float4*)(g_hidden + (size_t)node * NF);
        float4 hv = hid[lane];
        hv.x += tk * a0; hv.y += tk * a1; hv.z += tk * a2; hv.w += tk * a3;
        hid[lane] = hv;
    }
}

// ---------------- MLP layer 1: z1 = relu(hidden @ W1 + b1) ----------------
__global__ void k_mlp1(const float* __restrict__ B, const float* __restrict__ bias) {
    __shared__ float As[64][33];
    __shared__ float Bs[32][64];
    const float* __restrict__ A = g_hidden;
    float* __restrict__ C = g_z1;

    int tid = threadIdx.x;
    int brow = blockIdx.x * 64;
    int bcol = blockIdx.y * 64;
    int tr = (tid / 16) * 4;
    int tc = (tid % 16) * 4;

    float acc[4][4];
#pragma unroll
    for (int i = 0; i < 4; i++)
#pragma unroll
        for (int j = 0; j < 4; j++) acc[i][j] = 0.f;

    for (int k0 = 0; k0 < NF; k0 += 32) {
#pragma unroll
        for (int t = 0; t < 2; t++) {
            int i = tid + t * 256;
            int r = i / 8, c = (i % 8) * 4;
            float4 v;
            if (brow + r < NN)
                v = *(const float4*)&A[(size_t)(brow + r) * NF + k0 + c];
            else
                v = make_float4(0.f, 0.f, 0.f, 0.f);
            As[r][c] = v.x; As[r][c + 1] = v.y; As[r][c + 2] = v.z; As[r][c + 3] = v.w;
        }
#pragma unroll
        for (int t = 0; t < 2; t++) {
            int i = tid + t * 256;
            int r = i / 16, c = (i % 16) * 4;
            float4 v = *(const float4*)&B[(size_t)(k0 + r) * NH + bcol + c];
            *(float4*)&Bs[r][c] = v;
        }
        __syncthreads();
#pragma unroll
        for (int kk = 0; kk < 32; kk++) {
            float a[4];
#pragma unroll
            for (int i = 0; i < 4; i++) a[i] = As[tr + i][kk];
            float4 b = *(const float4*)&Bs[kk][tc];
#pragma unroll
            for (int i = 0; i < 4; i++) {
                acc[i][0] += a[i] * b.x;
                acc[i][1] += a[i] * b.y;
                acc[i][2] += a[i] * b.z;
                acc[i][3] += a[i] * b.w;
            }
        }
        __syncthreads();
    }

    float4 bb = *(const float4*)&bias[bcol + tc];
#pragma unroll
    for (int i = 0; i < 4; i++) {
        int r = brow + tr + i;
        if (r < NN) {
            float4 v;
            v.x = fmaxf(acc[i][0] + bb.x, 0.f);
            v.y = fmaxf(acc[i][1] + bb.y, 0.f);
            v.z = fmaxf(acc[i][2] + bb.z, 0.f);
            v.w = fmaxf(acc[i][3] + bb.w, 0.f);
            *(float4*)&C[(size_t)r * NH + bcol + tc] = v;
        }
    }
}

// ---------------- MLP layer 2 + log_softmax: thread per node ----------------
__global__ void k_mlp2(const float* __restrict__ W2, const float* __restrict__ b2,
                       float* __restrict__ out) {
    __shared__ float Ws[NH * NC];
    __shared__ float bs[NC];
    for (int i = threadIdx.x; i < NH * NC; i += blockDim.x) Ws[i] = W2[i];
    if (threadIdx.x < NC) bs[threadIdx.x] = b2[threadIdx.x];
    __syncthreads();

    int node = blockIdx.x * blockDim.x + threadIdx.x;
    if (node >= NN) return;

    float acc[NC];
#pragma unroll
    for (int j = 0; j < NC; j++) acc[j] = bs[j];

    const float4* z4 = (const float4*)(g_z1 + (size_t)node * NH);
    for (int kk = 0; kk < NH / 4; kk++) {
        float4 z = z4[kk];
        int base = (kk * 4) * NC;
#pragma unroll
        for (int j = 0; j < NC; j++) {
            acc[j] += z.x * Ws[base + j] + z.y * Ws[base + NC + j]
                    + z.z * Ws[base + 2 * NC + j] + z.w * Ws[base + 3 * NC + j];
        }
    }

    float m = -1e30f;
#pragma unroll
    for (int j = 0; j < NC; j++) m = fmaxf(m, acc[j]);
    float s = 0.f;
#pragma unroll
    for (int j = 0; j < NC; j++) s += expf(acc[j] - m);
    float ls = logf(s);
    float* o = out + (size_t)node * NC;
#pragma unroll
    for (int j = 0; j < NC; j++) o[j] = acc[j] - m - ls;
}

// ---------------- launch ----------------
extern "C" void kernel_launch(void* const* d_in, const int* in_sizes, int n_in,
                              void* d_out, int out_size) {
    const float* x    = (const float*)d_in[0];
    const void*  ei   = d_in[1];
    const float* temp = (const float*)d_in[2];
    const float* W1   = (const float*)d_in[3];
    const float* b1   = (const float*)d_in[4];
    const float* W2   = (const float*)d_in[5];
    const float* b2   = (const float*)d_in[6];
    float*       out  = (float*)d_out;

    const int TB = 256;
    const int NB_SCAN = (NN + 1023) / 1024;  // 49

    k_detect<<<1, 32>>>(ei);
    k_initcnt<<<(NN + TB - 1) / TB, TB>>>();
    k_convert<<<(NE + TB - 1) / TB, TB>>>(ei);
    k_dinv<<<(NN + TB - 1) / TB, TB>>>();
    k_scan1<<<NB_SCAN, 1024>>>();
    k_scan2<<<1, 64>>>(NB_SCAN);
    k_scan3<<<NB_SCAN, 1024>>>();
    k_zerocnt<<<(NN + TB - 1) / TB, TB>>>();
    k_fill<<<(NTOT + TB - 1) / TB, TB>>>();

    k_init_h<<<(NN * NF / 4 + TB - 1) / TB, TB>>>(x, temp);

    for (int k = 0; k < KHOPS; k++) {
        k_prop<<<(NN + 7) / 8, 256>>>(temp, k);
    }

    dim3 g1((NN + 63) / 64, NH / 64);
    k_mlp1<<<g1, 256>>>(W1, b1);

    k_mlp2<<<(NN + 127) / 128, 128>>>(W2, b2, out);
}